// round 13
// baseline (speedup 1.0000x reference)
#include <cuda_runtime.h>
#include <cstdint>
#include <math.h>

// Problem constants (fixed by the reference)
#define BATCH   2
#define SEQ     2048
#define EMB     512
#define HEADS   8
#define DHEAD   64
#define WINHALF 128         // WIN/2

#define M1 (BATCH*SEQ)      // 4096 rows
#define N1 (3*EMB)          // 1536 (qkv)
#define KDIM EMB            // 512

// Scratch: __device__ globals (no allocation allowed anywhere)
__device__ float g_qkv[(size_t)M1 * N1];      // tf32-rounded qkv   ~25 MB
__device__ float g_ctx[(size_t)M1 * EMB];     // tf32-rounded ctx    ~8 MB
__device__ float g_xr[(size_t)M1 * KDIM];     // tf32-rounded x      ~8 MB
__device__ float g_wqkvr[(size_t)KDIM * N1];  // tf32-rounded Wqkv   ~3 MB
__device__ float g_wor[(size_t)KDIM * EMB];   // tf32-rounded Wo     ~1 MB

// ===========================================================================
// Helpers: mma.sync tf32 (SM80-compatible path, valid on compute_100)
// ===========================================================================
__device__ __forceinline__ uint32_t f2tf32(float x) {
    uint32_t r;
    asm("cvt.rna.tf32.f32 %0, %1;" : "=r"(r) : "f"(x));
    return r;
}
__device__ __forceinline__ float tf32r(float x) {
    return __uint_as_float(f2tf32(x));
}

__device__ __forceinline__ void mma_tf32_16x8x8(
    float* c, uint32_t a0, uint32_t a1, uint32_t a2, uint32_t a3,
    uint32_t b0, uint32_t b1)
{
    asm volatile(
        "mma.sync.aligned.m16n8k8.row.col.f32.tf32.tf32.f32 "
        "{%0,%1,%2,%3}, {%4,%5,%6,%7}, {%8,%9}, {%0,%1,%2,%3};"
        : "+f"(c[0]), "+f"(c[1]), "+f"(c[2]), "+f"(c[3])
        : "r"(a0), "r"(a1), "r"(a2), "r"(a3), "r"(b0), "r"(b1));
}

__device__ __forceinline__ uint32_t smem_u32(const void* p) {
    return (uint32_t)__cvta_generic_to_shared(p);
}

#define CP_ASYNC16(dst_u32, src_ptr) \
    asm volatile("cp.async.cg.shared.global [%0], [%1], 16;" \
                 :: "r"(dst_u32), "l"(src_ptr))
#define CP_COMMIT() asm volatile("cp.async.commit_group;" ::: "memory")
#define CP_WAIT(n)  asm volatile("cp.async.wait_group %0;" :: "n"(n) : "memory")

// ===========================================================================
// Fused tf32 rounding pre-pass: one launch for x, Wqkv, Wo (range dispatch)
// ===========================================================================
#define NX4 (M1 * KDIM / 4)
#define NQ4 (KDIM * N1 / 4)
#define NO4 (KDIM * EMB / 4)

__global__ void round3_tf32_kernel(const float* __restrict__ x,
                                   const float* __restrict__ wq,
                                   const float* __restrict__ wo,
                                   float* __restrict__ xr,
                                   float* __restrict__ wqr,
                                   float* __restrict__ wor)
{
    int i = blockIdx.x * blockDim.x + threadIdx.x;
    const float4* src;
    float4* dst;
    if (i < NX4)                 { src = (const float4*)x  + i;
                                   dst = (float4*)xr  + i; }
    else if (i < NX4 + NQ4)      { src = (const float4*)wq + (i - NX4);
                                   dst = (float4*)wqr + (i - NX4); }
    else if (i < NX4 + NQ4 + NO4){ src = (const float4*)wo + (i - NX4 - NQ4);
                                   dst = (float4*)wor + (i - NX4 - NQ4); }
    else return;
    float4 v = *src;
    v.x = tf32r(v.x); v.y = tf32r(v.y);
    v.z = tf32r(v.z); v.w = tf32r(v.w);
    *dst = v;
}

// ===========================================================================
// tf32 tensor-core GEMM: C[M,N] = A[M,K] @ B[K,N] + bias[N]
// Inputs pre-rounded to tf32 -> no cvt in the mainloop.
// 128x64 CTA tile, BK=32, 2-stage cp.async, 8 warps (4x2), warp tile 32x32.
// 256 threads. smem 2*(128*36 + 32*72)*4 = 55,296 B -> 3 CTAs/SM.
// ===========================================================================
#define BM 128
#define BN 64
#define BK 32
#define APAD 36    // As row stride (floats)
#define BPAD 72    // Bs row stride (floats); 72%32=8 -> conflict-free frags

#define GEMM_SMEM_BYTES ((2 * BM * APAD + 2 * BK * BPAD) * (int)sizeof(float))

__global__ __launch_bounds__(256, 3) void mma_gemm_kernel(
    const float* __restrict__ A, const float* __restrict__ B,
    const float* __restrict__ bias, float* __restrict__ C,
    int M, int N, int K, int round_out)
{
    extern __shared__ float smem[];
    float* AsBase = smem;                    // 2 stages of BM*APAD
    float* BsBase = smem + 2 * BM * APAD;    // 2 stages of BK*BPAD

    const int tid  = threadIdx.x;
    const int lane = tid & 31;
    const int wid  = tid >> 5;
    const int wm   = wid & 3;            // warp row (4) -> 32 rows each
    const int wn   = wid >> 2;           // warp col (2) -> 32 cols each
    const int m0   = blockIdx.y * BM;
    const int n0   = blockIdx.x * BN;
    const int rq   = lane >> 2;          // 0..7
    const int cq   = lane & 3;           // 0..3

    const int bCol = wn * 32 + rq;

    float acc[2][4][4];
    #pragma unroll
    for (int mi = 0; mi < 2; mi++)
        #pragma unroll
        for (int ni = 0; ni < 4; ni++)
            #pragma unroll
            for (int r = 0; r < 4; r++) acc[mi][ni][r] = 0.f;

    const int nch = K / BK;   // 16

    auto load_tiles = [&](int s, int ch) {
        const int k0 = ch * BK;
        float* As_ = AsBase + s * BM * APAD;
        float* Bs_ = BsBase + s * BK * BPAD;
        // A: 128 rows x 32 floats -> 1024 float4, 4 per thread
        #pragma unroll
        for (int i = 0; i < 4; i++) {
            const int idx = tid + i * 256;
            const int row = idx >> 3;
            const int c4  = (idx & 7) << 2;
            const float* src = A + (size_t)(m0 + row) * K + k0 + c4;
            CP_ASYNC16(smem_u32(&As_[row * APAD + c4]), src);
        }
        // B: 32 rows x 64 floats -> 512 float4, 2 per thread
        #pragma unroll
        for (int i = 0; i < 2; i++) {
            const int idx = tid + i * 256;
            const int row = idx >> 4;
            const int c4  = (idx & 15) << 2;
            const float* src = B + (size_t)(k0 + row) * N + n0 + c4;
            CP_ASYNC16(smem_u32(&Bs_[row * BPAD + c4]), src);
        }
        CP_COMMIT();
    };

    load_tiles(0, 0);

    for (int ch = 0; ch < nch; ch++) {
        const int s = ch & 1;
        if (ch + 1 < nch) {
            load_tiles(s ^ 1, ch + 1);
            CP_WAIT(1);
        } else {
            CP_WAIT(0);
        }
        __syncthreads();

        const float* As_ = AsBase + s * BM * APAD;
        const float* Bs_ = BsBase + s * BK * BPAD;

        #pragma unroll
        for (int ks = 0; ks < 4; ks++) {
            const int k0 = ks * 8;
            uint32_t bf[4][2];
            #pragma unroll
            for (int ni = 0; ni < 4; ni++) {
                bf[ni][0] = __float_as_uint(Bs_[(k0 + cq)     * BPAD + bCol + ni * 8]);
                bf[ni][1] = __float_as_uint(Bs_[(k0 + cq + 4) * BPAD + bCol + ni * 8]);
            }
            uint32_t af[2][4];
            #pragma unroll
            for (int mi = 0; mi < 2; mi++) {
                const int rA = (wm * 32 + mi * 16 + rq) * APAD;
                const int rB = rA + 8 * APAD;
                af[mi][0] = __float_as_uint(As_[rA + k0 + cq]);
                af[mi][1] = __float_as_uint(As_[rB + k0 + cq]);
                af[mi][2] = __float_as_uint(As_[rA + k0 + cq + 4]);
                af[mi][3] = __float_as_uint(As_[rB + k0 + cq + 4]);
            }
            #pragma unroll
            for (int mi = 0; mi < 2; mi++)
                #pragma unroll
                for (int ni = 0; ni < 4; ni++)
                    mma_tf32_16x8x8(acc[mi][ni], af[mi][0], af[mi][1],
                                    af[mi][2], af[mi][3],
                                    bf[ni][0], bf[ni][1]);
        }
        __syncthreads();
    }

    // Epilogue
    #pragma unroll
    for (int mi = 0; mi < 2; mi++) {
        const int crow = m0 + wm * 32 + mi * 16 + rq;
        const int ccol = n0 + wn * 32 + (cq << 1);
        #pragma unroll
        for (int ni = 0; ni < 4; ni++) {
            const int col = ccol + ni * 8;
            const float bx = bias[col], by = bias[col + 1];
            float2 v0, v1;
            v0.x = acc[mi][ni][0] + bx;  v0.y = acc[mi][ni][1] + by;
            v1.x = acc[mi][ni][2] + bx;  v1.y = acc[mi][ni][3] + by;
            if (round_out) {
                v0.x = tf32r(v0.x); v0.y = tf32r(v0.y);
                v1.x = tf32r(v1.x); v1.y = tf32r(v1.y);
            }
            *(float2*)(C + (size_t)crow       * N + col) = v0;
            *(float2*)(C + (size_t)(crow + 8) * N + col) = v1;
        }
    }
}

// ===========================================================================
// Fused banded attention on tensor cores (flash-style, tf32 mma).
// 128-query tile, 4 warps, each warp owns 32 rows (2 x m16 tiles).
// 6 key-tiles of 64 cover the band (vs 10 per 128 rows at the old 64-tile).
// qkv pre-rounded tf32; ctx written tf32-rounded for GEMM2.
// ===========================================================================
#define QTILE 128
#define QPAD 68
#define VPAD 72
#define ATT_SMEM_BYTES ((2 * QTILE * QPAD + 64 * QPAD + 64 * VPAD) * (int)sizeof(float) + 64 * (int)sizeof(int))

__global__ __launch_bounds__(128) void attn_mma_kernel(
    const float* __restrict__ qkv, const int* __restrict__ pmask,
    float* __restrict__ ctx)
{
    extern __shared__ float sm[];
    float* Qs = sm;                          // [128][68]
    float* Ks = Qs + QTILE * QPAD;           // [64][68]
    float* Ps = Ks + 64 * QPAD;              // [128][68]
    float* Vs = Ps + QTILE * QPAD;           // [64][72]
    int*   pms = (int*)(Vs + 64 * VPAD);     // [64]

    const int tid  = threadIdx.x;
    const int lane = tid & 31;
    const int wid  = tid >> 5;
    const int rq   = lane >> 2;    // 0..7
    const int cq   = lane & 3;     // 0..3
    const int wr0  = wid * 32;     // warp owns rows wr0..wr0+31

    const int r0 = blockIdx.x * QTILE;
    const int b  = blockIdx.y >> 3;
    const int h  = blockIdx.y & 7;

    const float* base = qkv + (size_t)b * SEQ * N1 + h * (3 * DHEAD);

    // Load Q tile: 128 rows x 64 cols = 2048 float4, 16 per thread
    #pragma unroll
    for (int i = 0; i < 16; i++) {
        const int idx = tid + i * 128;
        const int row = idx >> 4;
        const int c4  = (idx & 15) << 2;
        float4 v = *(const float4*)(base + (size_t)(r0 + row) * N1 + c4);
        float* q = Qs + row * QPAD + c4;
        q[0] = v.x * 0.125f; q[1] = v.y * 0.125f;
        q[2] = v.z * 0.125f; q[3] = v.w * 0.125f;
    }

    float o[2][8][4];
    #pragma unroll
    for (int mi = 0; mi < 2; mi++)
        #pragma unroll
        for (int ni = 0; ni < 8; ni++)
            #pragma unroll
            for (int r = 0; r < 4; r++) o[mi][ni][r] = 0.f;

    float mst[2][2], lst[2][2];
    #pragma unroll
    for (int mi = 0; mi < 2; mi++) {
        mst[mi][0] = -1e30f; mst[mi][1] = -1e30f;
        lst[mi][0] = 0.f;    lst[mi][1] = 0.f;
    }
    int gr[2][2];
    #pragma unroll
    for (int mi = 0; mi < 2; mi++) {
        gr[mi][0] = r0 + wr0 + mi * 16 + rq;
        gr[mi][1] = gr[mi][0] + 8;
    }

    for (int kt = 0; kt < 6; kt++) {
        const int c0 = r0 - WINHALF + kt * 64;
        if (c0 + 63 < 0 || c0 >= SEQ) continue;   // uniform across block

        __syncthreads();   // Q ready (first pass) / prev tile fully consumed

        // Load K,V tile (zero-fill out-of-range); pmask tile
        #pragma unroll
        for (int i = 0; i < 8; i++) {
            const int idx = tid + i * 128;
            const int row = idx >> 4;
            const int c4  = (idx & 15) << 2;
            const int gc  = c0 + row;
            float4 kv = make_float4(0.f, 0.f, 0.f, 0.f);
            float4 vv = make_float4(0.f, 0.f, 0.f, 0.f);
            if (gc >= 0 && gc < SEQ) {
                kv = *(const float4*)(base + (size_t)gc * N1 + DHEAD + c4);
                vv = *(const float4*)(base + (size_t)gc * N1 + 2 * DHEAD + c4);
            }
            float* kp = Ks + row * QPAD + c4;
            kp[0] = kv.x; kp[1] = kv.y; kp[2] = kv.z; kp[3] = kv.w;
            float* vp = Vs + row * VPAD + c4;
            vp[0] = vv.x; vp[1] = vv.y; vp[2] = vv.z; vp[3] = vv.w;
        }
        if (tid < 64) {
            const int gc = c0 + tid;
            pms[tid] = (gc >= 0 && gc < SEQ) ? pmask[b * SEQ + gc] : 0;
        }
        __syncthreads();

        // ---- S = Q @ K^T : rows wr0..wr0+31, cols 0..63 ----
        float s[2][8][4];
        #pragma unroll
        for (int mi = 0; mi < 2; mi++)
            #pragma unroll
            for (int ni = 0; ni < 8; ni++)
                #pragma unroll
                for (int r = 0; r < 4; r++) s[mi][ni][r] = 0.f;

        #pragma unroll
        for (int ks = 0; ks < 8; ks++) {
            const int k0 = ks * 8;
            uint32_t af[2][4];
            #pragma unroll
            for (int mi = 0; mi < 2; mi++) {
                const int rA = (wr0 + mi * 16 + rq) * QPAD;
                const int rB = rA + 8 * QPAD;
                af[mi][0] = __float_as_uint(Qs[rA + k0 + cq]);
                af[mi][1] = __float_as_uint(Qs[rB + k0 + cq]);
                af[mi][2] = __float_as_uint(Qs[rA + k0 + cq + 4]);
                af[mi][3] = __float_as_uint(Qs[rB + k0 + cq + 4]);
            }
            #pragma unroll
            for (int ni = 0; ni < 8; ni++) {
                uint32_t b0 = __float_as_uint(Ks[(ni * 8 + rq) * QPAD + k0 + cq]);
                uint32_t b1 = __float_as_uint(Ks[(ni * 8 + rq) * QPAD + k0 + cq + 4]);
                mma_tf32_16x8x8(s[0][ni], af[0][0], af[0][1], af[0][2], af[0][3], b0, b1);
                mma_tf32_16x8x8(s[1][ni], af[1][0], af[1][1], af[1][2], af[1][3], b0, b1);
            }
        }

        // ---- band + padding mask ----
        #pragma unroll
        for (int mi = 0; mi < 2; mi++)
            #pragma unroll
            for (int ni = 0; ni < 8; ni++)
                #pragma unroll
                for (int d = 0; d < 2; d++) {
                    const int lc = ni * 8 + 2 * cq + d;
                    const int gc = c0 + lc;
                    const bool cvalid = (pms[lc] == 1);
                    const int d0 = gc - gr[mi][0];
                    const int d1 = gc - gr[mi][1];
                    if (!cvalid || d0 > WINHALF || d0 < -WINHALF) s[mi][ni][d]     = -1e30f;
                    if (!cvalid || d1 > WINHALF || d1 < -WINHALF) s[mi][ni][d + 2] = -1e30f;
                }

        // ---- online softmax (quad-local), exp in place ----
        #pragma unroll
        for (int mi = 0; mi < 2; mi++) {
            float tm0 = -1e30f, tm1 = -1e30f;
            #pragma unroll
            for (int ni = 0; ni < 8; ni++) {
                tm0 = fmaxf(tm0, fmaxf(s[mi][ni][0], s[mi][ni][1]));
                tm1 = fmaxf(tm1, fmaxf(s[mi][ni][2], s[mi][ni][3]));
            }
            tm0 = fmaxf(tm0, __shfl_xor_sync(0xffffffffu, tm0, 1));
            tm0 = fmaxf(tm0, __shfl_xor_sync(0xffffffffu, tm0, 2));
            tm1 = fmaxf(tm1, __shfl_xor_sync(0xffffffffu, tm1, 1));
            tm1 = fmaxf(tm1, __shfl_xor_sync(0xffffffffu, tm1, 2));

            const float mn0 = fmaxf(mst[mi][0], tm0);
            const float mn1 = fmaxf(mst[mi][1], tm1);
            const float sc0 = __expf(mst[mi][0] - mn0);
            const float sc1 = __expf(mst[mi][1] - mn1);
            mst[mi][0] = mn0; mst[mi][1] = mn1;

            float ts0 = 0.f, ts1 = 0.f;
            #pragma unroll
            for (int ni = 0; ni < 8; ni++) {
                s[mi][ni][0] = (s[mi][ni][0] > -1e29f) ? __expf(s[mi][ni][0] - mn0) : 0.f;
                s[mi][ni][1] = (s[mi][ni][1] > -1e29f) ? __expf(s[mi][ni][1] - mn0) : 0.f;
                s[mi][ni][2] = (s[mi][ni][2] > -1e29f) ? __expf(s[mi][ni][2] - mn1) : 0.f;
                s[mi][ni][3] = (s[mi][ni][3] > -1e29f) ? __expf(s[mi][ni][3] - mn1) : 0.f;
                ts0 += s[mi][ni][0] + s[mi][ni][1];
                ts1 += s[mi][ni][2] + s[mi][ni][3];
            }
            ts0 += __shfl_xor_sync(0xffffffffu, ts0, 1);
            ts0 += __shfl_xor_sync(0xffffffffu, ts0, 2);
            ts1 += __shfl_xor_sync(0xffffffffu, ts1, 1);
            ts1 += __shfl_xor_sync(0xffffffffu, ts1, 2);
            lst[mi][0] = lst[mi][0] * sc0 + ts0;
            lst[mi][1] = lst[mi][1] * sc1 + ts1;

            #pragma unroll
            for (int ni = 0; ni < 8; ni++) {
                o[mi][ni][0] *= sc0; o[mi][ni][1] *= sc0;
                o[mi][ni][2] *= sc1; o[mi][ni][3] *= sc1;
            }
        }

        // ---- P to warp-private smem rows (tf32-rounded) ----
        #pragma unroll
        for (int mi = 0; mi < 2; mi++)
            #pragma unroll
            for (int ni = 0; ni < 8; ni++) {
                const int col = ni * 8 + 2 * cq;
                const int rA = (wr0 + mi * 16 + rq) * QPAD;
                const int rB = rA + 8 * QPAD;
                Ps[rA + col]     = tf32r(s[mi][ni][0]);
                Ps[rA + col + 1] = tf32r(s[mi][ni][1]);
                Ps[rB + col]     = tf32r(s[mi][ni][2]);
                Ps[rB + col + 1] = tf32r(s[mi][ni][3]);
            }
        __syncwarp();

        // ---- O += P @ V ----
        #pragma unroll
        for (int ks = 0; ks < 8; ks++) {
            const int k0 = ks * 8;
            uint32_t af[2][4];
            #pragma unroll
            for (int mi = 0; mi < 2; mi++) {
                const int rA = (wr0 + mi * 16 + rq) * QPAD;
                const int rB = rA + 8 * QPAD;
                af[mi][0] = __float_as_uint(Ps[rA + k0 + cq]);
                af[mi][1] = __float_as_uint(Ps[rB + k0 + cq]);
                af[mi][2] = __float_as_uint(Ps[rA + k0 + cq + 4]);
                af[mi][3] = __float_as_uint(Ps[rB + k0 + cq + 4]);
            }
            #pragma unroll
            for (int ni = 0; ni < 8; ni++) {
                uint32_t b0 = __float_as_uint(Vs[(k0 + cq)     * VPAD + ni * 8 + rq]);
                uint32_t b1 = __float_as_uint(Vs[(k0 + cq + 4) * VPAD + ni * 8 + rq]);
                mma_tf32_16x8x8(o[0][ni], af[0][0], af[0][1], af[0][2], af[0][3], b0, b1);
                mma_tf32_16x8x8(o[1][ni], af[1][0], af[1][1], af[1][2], af[1][3], b0, b1);
            }
        }
        __syncwarp();
    }

    // ---- normalize + write ctx [B,S,E] (tf32-rounded for GEMM2) ----
    #pragma unroll
    for (int mi = 0; mi < 2; mi++) {
        #pragma unroll
        for (int hh = 0; hh < 2; hh++) {
            const int row = gr[mi][hh];
            const float l = lst[mi][hh];
            const int pm = pmask[b * SEQ + row];
            const float inv = (l > 0.f && pm == 1) ? 1.f / l : 0.f;
            float* cp = ctx + (size_t)(b * SEQ + row) * EMB + h * DHEAD;
            #pragma unroll
            for (int ni = 0; ni < 8; ni++) {
                const int col = ni * 8 + 2 * cq;
                float2 v;
                v.x = tf32r(o[mi][ni][2 * hh]     * inv);
                v.y = tf32r(o[mi][ni][2 * hh + 1] * inv);
                *(float2*)(cp + col) = v;
            }
        }
    }
}

// ---------------------------------------------------------------------------
// Launch
// ---------------------------------------------------------------------------
extern "C" void kernel_launch(void* const* d_in, const int* in_sizes, int n_in,
                              void* d_out, int out_size)
{
    const float* x     = (const float*)d_in[0];
    const int*   pmask = (const int*)  d_in[1];
    const float* Wqkv  = (const float*)d_in[2];
    const float* bqkv  = (const float*)d_in[3];
    const float* Wo    = (const float*)d_in[4];
    const float* bo    = (const float*)d_in[5];
    float* out = (float*)d_out;

    float *qkv, *ctx, *xr, *wqkvr, *wor;
    cudaGetSymbolAddress((void**)&qkv,   g_qkv);
    cudaGetSymbolAddress((void**)&ctx,   g_ctx);
    cudaGetSymbolAddress((void**)&xr,    g_xr);
    cudaGetSymbolAddress((void**)&wqkvr, g_wqkvr);
    cudaGetSymbolAddress((void**)&wor,   g_wor);

    cudaFuncSetAttribute(mma_gemm_kernel,
                         cudaFuncAttributeMaxDynamicSharedMemorySize,
                         GEMM_SMEM_BYTES);
    cudaFuncSetAttribute(attn_mma_kernel,
                         cudaFuncAttributeMaxDynamicSharedMemorySize,
                         ATT_SMEM_BYTES);

    // 0) tf32 pre-round, single launch (x, Wqkv, Wo)
    {
        const int total = NX4 + NQ4 + NO4;
        round3_tf32_kernel<<<(total + 255) / 256, 256>>>(x, Wqkv, Wo,
                                                         xr, wqkvr, wor);
    }

    // 1) QKV projection (tf32 mma.sync), output tf32-rounded
    {
        dim3 grid(N1 / BN, M1 / BM);   // (24, 32) = 768 CTAs
        mma_gemm_kernel<<<grid, 256, GEMM_SMEM_BYTES>>>(xr, wqkvr, bqkv, qkv,
                                                        M1, N1, KDIM, 1);
    }

    // 2) Banded attention (tensor-core flash, 128-query tiles)
    {
        dim3 grid(SEQ / QTILE, BATCH * HEADS);   // (16, 16) = 256 CTAs
        attn_mma_kernel<<<grid, 128, ATT_SMEM_BYTES>>>(qkv, pmask, ctx);
    }

    // 3) Output projection (tf32 mma.sync), fp32 output
    {
        dim3 grid(EMB / BN, M1 / BM);   // (8, 32) = 256 CTAs
        mma_gemm_kernel<<<grid, 256, GEMM_SMEM_BYTES>>>(ctx, wor, bo, out,
                                                        M1, EMB, KDIM, 0);
    }
}

// round 14
// speedup vs baseline: 1.0023x; 1.0023x over previous
#include <cuda_runtime.h>
#include <cstdint>
#include <math.h>

// Problem constants (fixed by the reference)
#define BATCH   2
#define SEQ     2048
#define EMB     512
#define HEADS   8
#define DHEAD   64
#define WINHALF 128         // WIN/2

#define M1 (BATCH*SEQ)      // 4096 rows
#define N1 (3*EMB)          // 1536 (qkv)
#define KDIM EMB            // 512

// Scratch: __device__ globals (no allocation allowed anywhere)
__device__ float g_qkv[(size_t)M1 * N1];      // tf32-rounded qkv   ~25 MB
__device__ float g_ctx[(size_t)M1 * EMB];     // tf32-rounded ctx    ~8 MB
__device__ float g_xr[(size_t)M1 * KDIM];     // tf32-rounded x      ~8 MB
__device__ float g_wqkvr[(size_t)KDIM * N1];  // tf32-rounded Wqkv   ~3 MB
__device__ float g_wor[(size_t)KDIM * EMB];   // tf32-rounded Wo     ~1 MB

// ===========================================================================
// Helpers: mma.sync tf32 (SM80-compatible path, valid on compute_100)
// ===========================================================================
__device__ __forceinline__ uint32_t f2tf32(float x) {
    uint32_t r;
    asm("cvt.rna.tf32.f32 %0, %1;" : "=r"(r) : "f"(x));
    return r;
}
__device__ __forceinline__ float tf32r(float x) {
    return __uint_as_float(f2tf32(x));
}

__device__ __forceinline__ void mma_tf32_16x8x8(
    float* c, uint32_t a0, uint32_t a1, uint32_t a2, uint32_t a3,
    uint32_t b0, uint32_t b1)
{
    asm volatile(
        "mma.sync.aligned.m16n8k8.row.col.f32.tf32.tf32.f32 "
        "{%0,%1,%2,%3}, {%4,%5,%6,%7}, {%8,%9}, {%0,%1,%2,%3};"
        : "+f"(c[0]), "+f"(c[1]), "+f"(c[2]), "+f"(c[3])
        : "r"(a0), "r"(a1), "r"(a2), "r"(a3), "r"(b0), "r"(b1));
}

__device__ __forceinline__ uint32_t smem_u32(const void* p) {
    return (uint32_t)__cvta_generic_to_shared(p);
}

#define CP_ASYNC16(dst_u32, src_ptr) \
    asm volatile("cp.async.cg.shared.global [%0], [%1], 16;" \
                 :: "r"(dst_u32), "l"(src_ptr))
#define CP_COMMIT() asm volatile("cp.async.commit_group;" ::: "memory")
#define CP_WAIT(n)  asm volatile("cp.async.wait_group %0;" :: "n"(n) : "memory")

// ===========================================================================
// Fused tf32 rounding pre-pass: one launch for x, Wqkv, Wo (range dispatch)
// ===========================================================================
#define NX4 (M1 * KDIM / 4)
#define NQ4 (KDIM * N1 / 4)
#define NO4 (KDIM * EMB / 4)

__global__ void round3_tf32_kernel(const float* __restrict__ x,
                                   const float* __restrict__ wq,
                                   const float* __restrict__ wo,
                                   float* __restrict__ xr,
                                   float* __restrict__ wqr,
                                   float* __restrict__ wor)
{
    int i = blockIdx.x * blockDim.x + threadIdx.x;
    const float4* src;
    float4* dst;
    if (i < NX4)                 { src = (const float4*)x  + i;
                                   dst = (float4*)xr  + i; }
    else if (i < NX4 + NQ4)      { src = (const float4*)wq + (i - NX4);
                                   dst = (float4*)wqr + (i - NX4); }
    else if (i < NX4 + NQ4 + NO4){ src = (const float4*)wo + (i - NX4 - NQ4);
                                   dst = (float4*)wor + (i - NX4 - NQ4); }
    else return;
    float4 v = *src;
    v.x = tf32r(v.x); v.y = tf32r(v.y);
    v.z = tf32r(v.z); v.w = tf32r(v.w);
    *dst = v;
}

// ===========================================================================
// tf32 tensor-core GEMM: C[M,N] = A[M,K] @ B[K,N] + bias[N]
// Inputs pre-rounded to tf32 -> no cvt in the mainloop.
// 128x64 CTA tile, BK=32, 2-stage cp.async, 8 warps (4x2), warp tile 32x32.
// 256 threads. smem 2*(128*36 + 32*72)*4 = 55,296 B -> 3 CTAs/SM.
// ===========================================================================
#define BM 128
#define BN 64
#define BK 32
#define APAD 36    // As row stride (floats)
#define BPAD 72    // Bs row stride (floats); 72%32=8 -> conflict-free frags

#define GEMM_SMEM_BYTES ((2 * BM * APAD + 2 * BK * BPAD) * (int)sizeof(float))

__global__ __launch_bounds__(256, 3) void mma_gemm_kernel(
    const float* __restrict__ A, const float* __restrict__ B,
    const float* __restrict__ bias, float* __restrict__ C,
    int M, int N, int K, int round_out)
{
    extern __shared__ float smem[];
    float* AsBase = smem;                    // 2 stages of BM*APAD
    float* BsBase = smem + 2 * BM * APAD;    // 2 stages of BK*BPAD

    const int tid  = threadIdx.x;
    const int lane = tid & 31;
    const int wid  = tid >> 5;
    const int wm   = wid & 3;            // warp row (4) -> 32 rows each
    const int wn   = wid >> 2;           // warp col (2) -> 32 cols each
    const int m0   = blockIdx.y * BM;
    const int n0   = blockIdx.x * BN;
    const int rq   = lane >> 2;          // 0..7
    const int cq   = lane & 3;           // 0..3

    const int bCol = wn * 32 + rq;

    float acc[2][4][4];
    #pragma unroll
    for (int mi = 0; mi < 2; mi++)
        #pragma unroll
        for (int ni = 0; ni < 4; ni++)
            #pragma unroll
            for (int r = 0; r < 4; r++) acc[mi][ni][r] = 0.f;

    const int nch = K / BK;   // 16

    auto load_tiles = [&](int s, int ch) {
        const int k0 = ch * BK;
        float* As_ = AsBase + s * BM * APAD;
        float* Bs_ = BsBase + s * BK * BPAD;
        // A: 128 rows x 32 floats -> 1024 float4, 4 per thread
        #pragma unroll
        for (int i = 0; i < 4; i++) {
            const int idx = tid + i * 256;
            const int row = idx >> 3;
            const int c4  = (idx & 7) << 2;
            const float* src = A + (size_t)(m0 + row) * K + k0 + c4;
            CP_ASYNC16(smem_u32(&As_[row * APAD + c4]), src);
        }
        // B: 32 rows x 64 floats -> 512 float4, 2 per thread
        #pragma unroll
        for (int i = 0; i < 2; i++) {
            const int idx = tid + i * 256;
            const int row = idx >> 4;
            const int c4  = (idx & 15) << 2;
            const float* src = B + (size_t)(k0 + row) * N + n0 + c4;
            CP_ASYNC16(smem_u32(&Bs_[row * BPAD + c4]), src);
        }
        CP_COMMIT();
    };

    load_tiles(0, 0);

    for (int ch = 0; ch < nch; ch++) {
        const int s = ch & 1;
        if (ch + 1 < nch) {
            load_tiles(s ^ 1, ch + 1);
            CP_WAIT(1);
        } else {
            CP_WAIT(0);
        }
        __syncthreads();

        const float* As_ = AsBase + s * BM * APAD;
        const float* Bs_ = BsBase + s * BK * BPAD;

        #pragma unroll
        for (int ks = 0; ks < 4; ks++) {
            const int k0 = ks * 8;
            uint32_t bf[4][2];
            #pragma unroll
            for (int ni = 0; ni < 4; ni++) {
                bf[ni][0] = __float_as_uint(Bs_[(k0 + cq)     * BPAD + bCol + ni * 8]);
                bf[ni][1] = __float_as_uint(Bs_[(k0 + cq + 4) * BPAD + bCol + ni * 8]);
            }
            uint32_t af[2][4];
            #pragma unroll
            for (int mi = 0; mi < 2; mi++) {
                const int rA = (wm * 32 + mi * 16 + rq) * APAD;
                const int rB = rA + 8 * APAD;
                af[mi][0] = __float_as_uint(As_[rA + k0 + cq]);
                af[mi][1] = __float_as_uint(As_[rB + k0 + cq]);
                af[mi][2] = __float_as_uint(As_[rA + k0 + cq + 4]);
                af[mi][3] = __float_as_uint(As_[rB + k0 + cq + 4]);
            }
            #pragma unroll
            for (int mi = 0; mi < 2; mi++)
                #pragma unroll
                for (int ni = 0; ni < 4; ni++)
                    mma_tf32_16x8x8(acc[mi][ni], af[mi][0], af[mi][1],
                                    af[mi][2], af[mi][3],
                                    bf[ni][0], bf[ni][1]);
        }
        __syncthreads();
    }

    // Epilogue
    #pragma unroll
    for (int mi = 0; mi < 2; mi++) {
        const int crow = m0 + wm * 32 + mi * 16 + rq;
        const int ccol = n0 + wn * 32 + (cq << 1);
        #pragma unroll
        for (int ni = 0; ni < 4; ni++) {
            const int col = ccol + ni * 8;
            const float bx = bias[col], by = bias[col + 1];
            float2 v0, v1;
            v0.x = acc[mi][ni][0] + bx;  v0.y = acc[mi][ni][1] + by;
            v1.x = acc[mi][ni][2] + bx;  v1.y = acc[mi][ni][3] + by;
            if (round_out) {
                v0.x = tf32r(v0.x); v0.y = tf32r(v0.y);
                v1.x = tf32r(v1.x); v1.y = tf32r(v1.y);
            }
            *(float2*)(C + (size_t)crow       * N + col) = v0;
            *(float2*)(C + (size_t)(crow + 8) * N + col) = v1;
        }
    }
}

// ===========================================================================
// Fused banded attention on tensor cores (flash-style, tf32 mma).
// 128-query tile, 4 warps, each warp owns 32 rows (2 x m16 tiles).
// 6 key-tiles of 64 cover the band (vs 10 per 128 rows at the old 64-tile).
// qkv pre-rounded tf32; ctx written tf32-rounded for GEMM2.
// ===========================================================================
#define QTILE 128
#define QPAD 68
#define VPAD 72
#define ATT_SMEM_BYTES ((2 * QTILE * QPAD + 64 * QPAD + 64 * VPAD) * (int)sizeof(float) + 64 * (int)sizeof(int))

__global__ __launch_bounds__(128) void attn_mma_kernel(
    const float* __restrict__ qkv, const int* __restrict__ pmask,
    float* __restrict__ ctx)
{
    extern __shared__ float sm[];
    float* Qs = sm;                          // [128][68]
    float* Ks = Qs + QTILE * QPAD;           // [64][68]
    float* Ps = Ks + 64 * QPAD;              // [128][68]
    float* Vs = Ps + QTILE * QPAD;           // [64][72]
    int*   pms = (int*)(Vs + 64 * VPAD);     // [64]

    const int tid  = threadIdx.x;
    const int lane = tid & 31;
    const int wid  = tid >> 5;
    const int rq   = lane >> 2;    // 0..7
    const int cq   = lane & 3;     // 0..3
    const int wr0  = wid * 32;     // warp owns rows wr0..wr0+31

    const int r0 = blockIdx.x * QTILE;
    const int b  = blockIdx.y >> 3;
    const int h  = blockIdx.y & 7;

    const float* base = qkv + (size_t)b * SEQ * N1 + h * (3 * DHEAD);

    // Load Q tile: 128 rows x 64 cols = 2048 float4, 16 per thread
    #pragma unroll
    for (int i = 0; i < 16; i++) {
        const int idx = tid + i * 128;
        const int row = idx >> 4;
        const int c4  = (idx & 15) << 2;
        float4 v = *(const float4*)(base + (size_t)(r0 + row) * N1 + c4);
        float* q = Qs + row * QPAD + c4;
        q[0] = v.x * 0.125f; q[1] = v.y * 0.125f;
        q[2] = v.z * 0.125f; q[3] = v.w * 0.125f;
    }

    float o[2][8][4];
    #pragma unroll
    for (int mi = 0; mi < 2; mi++)
        #pragma unroll
        for (int ni = 0; ni < 8; ni++)
            #pragma unroll
            for (int r = 0; r < 4; r++) o[mi][ni][r] = 0.f;

    float mst[2][2], lst[2][2];
    #pragma unroll
    for (int mi = 0; mi < 2; mi++) {
        mst[mi][0] = -1e30f; mst[mi][1] = -1e30f;
        lst[mi][0] = 0.f;    lst[mi][1] = 0.f;
    }
    int gr[2][2];
    #pragma unroll
    for (int mi = 0; mi < 2; mi++) {
        gr[mi][0] = r0 + wr0 + mi * 16 + rq;
        gr[mi][1] = gr[mi][0] + 8;
    }

    for (int kt = 0; kt < 6; kt++) {
        const int c0 = r0 - WINHALF + kt * 64;
        if (c0 + 63 < 0 || c0 >= SEQ) continue;   // uniform across block

        __syncthreads();   // Q ready (first pass) / prev tile fully consumed

        // Load K,V tile (zero-fill out-of-range); pmask tile
        #pragma unroll
        for (int i = 0; i < 8; i++) {
            const int idx = tid + i * 128;
            const int row = idx >> 4;
            const int c4  = (idx & 15) << 2;
            const int gc  = c0 + row;
            float4 kv = make_float4(0.f, 0.f, 0.f, 0.f);
            float4 vv = make_float4(0.f, 0.f, 0.f, 0.f);
            if (gc >= 0 && gc < SEQ) {
                kv = *(const float4*)(base + (size_t)gc * N1 + DHEAD + c4);
                vv = *(const float4*)(base + (size_t)gc * N1 + 2 * DHEAD + c4);
            }
            float* kp = Ks + row * QPAD + c4;
            kp[0] = kv.x; kp[1] = kv.y; kp[2] = kv.z; kp[3] = kv.w;
            float* vp = Vs + row * VPAD + c4;
            vp[0] = vv.x; vp[1] = vv.y; vp[2] = vv.z; vp[3] = vv.w;
        }
        if (tid < 64) {
            const int gc = c0 + tid;
            pms[tid] = (gc >= 0 && gc < SEQ) ? pmask[b * SEQ + gc] : 0;
        }
        __syncthreads();

        // ---- S = Q @ K^T : rows wr0..wr0+31, cols 0..63 ----
        float s[2][8][4];
        #pragma unroll
        for (int mi = 0; mi < 2; mi++)
            #pragma unroll
            for (int ni = 0; ni < 8; ni++)
                #pragma unroll
                for (int r = 0; r < 4; r++) s[mi][ni][r] = 0.f;

        #pragma unroll
        for (int ks = 0; ks < 8; ks++) {
            const int k0 = ks * 8;
            uint32_t af[2][4];
            #pragma unroll
            for (int mi = 0; mi < 2; mi++) {
                const int rA = (wr0 + mi * 16 + rq) * QPAD;
                const int rB = rA + 8 * QPAD;
                af[mi][0] = __float_as_uint(Qs[rA + k0 + cq]);
                af[mi][1] = __float_as_uint(Qs[rB + k0 + cq]);
                af[mi][2] = __float_as_uint(Qs[rA + k0 + cq + 4]);
                af[mi][3] = __float_as_uint(Qs[rB + k0 + cq + 4]);
            }
            #pragma unroll
            for (int ni = 0; ni < 8; ni++) {
                uint32_t b0 = __float_as_uint(Ks[(ni * 8 + rq) * QPAD + k0 + cq]);
                uint32_t b1 = __float_as_uint(Ks[(ni * 8 + rq) * QPAD + k0 + cq + 4]);
                mma_tf32_16x8x8(s[0][ni], af[0][0], af[0][1], af[0][2], af[0][3], b0, b1);
                mma_tf32_16x8x8(s[1][ni], af[1][0], af[1][1], af[1][2], af[1][3], b0, b1);
            }
        }

        // ---- band + padding mask ----
        #pragma unroll
        for (int mi = 0; mi < 2; mi++)
            #pragma unroll
            for (int ni = 0; ni < 8; ni++)
                #pragma unroll
                for (int d = 0; d < 2; d++) {
                    const int lc = ni * 8 + 2 * cq + d;
                    const int gc = c0 + lc;
                    const bool cvalid = (pms[lc] == 1);
                    const int d0 = gc - gr[mi][0];
                    const int d1 = gc - gr[mi][1];
                    if (!cvalid || d0 > WINHALF || d0 < -WINHALF) s[mi][ni][d]     = -1e30f;
                    if (!cvalid || d1 > WINHALF || d1 < -WINHALF) s[mi][ni][d + 2] = -1e30f;
                }

        // ---- online softmax (quad-local), exp in place ----
        #pragma unroll
        for (int mi = 0; mi < 2; mi++) {
            float tm0 = -1e30f, tm1 = -1e30f;
            #pragma unroll
            for (int ni = 0; ni < 8; ni++) {
                tm0 = fmaxf(tm0, fmaxf(s[mi][ni][0], s[mi][ni][1]));
                tm1 = fmaxf(tm1, fmaxf(s[mi][ni][2], s[mi][ni][3]));
            }
            tm0 = fmaxf(tm0, __shfl_xor_sync(0xffffffffu, tm0, 1));
            tm0 = fmaxf(tm0, __shfl_xor_sync(0xffffffffu, tm0, 2));
            tm1 = fmaxf(tm1, __shfl_xor_sync(0xffffffffu, tm1, 1));
            tm1 = fmaxf(tm1, __shfl_xor_sync(0xffffffffu, tm1, 2));

            const float mn0 = fmaxf(mst[mi][0], tm0);
            const float mn1 = fmaxf(mst[mi][1], tm1);
            const float sc0 = __expf(mst[mi][0] - mn0);
            const float sc1 = __expf(mst[mi][1] - mn1);
            mst[mi][0] = mn0; mst[mi][1] = mn1;

            float ts0 = 0.f, ts1 = 0.f;
            #pragma unroll
            for (int ni = 0; ni < 8; ni++) {
                s[mi][ni][0] = (s[mi][ni][0] > -1e29f) ? __expf(s[mi][ni][0] - mn0) : 0.f;
                s[mi][ni][1] = (s[mi][ni][1] > -1e29f) ? __expf(s[mi][ni][1] - mn0) : 0.f;
                s[mi][ni][2] = (s[mi][ni][2] > -1e29f) ? __expf(s[mi][ni][2] - mn1) : 0.f;
                s[mi][ni][3] = (s[mi][ni][3] > -1e29f) ? __expf(s[mi][ni][3] - mn1) : 0.f;
                ts0 += s[mi][ni][0] + s[mi][ni][1];
                ts1 += s[mi][ni][2] + s[mi][ni][3];
            }
            ts0 += __shfl_xor_sync(0xffffffffu, ts0, 1);
            ts0 += __shfl_xor_sync(0xffffffffu, ts0, 2);
            ts1 += __shfl_xor_sync(0xffffffffu, ts1, 1);
            ts1 += __shfl_xor_sync(0xffffffffu, ts1, 2);
            lst[mi][0] = lst[mi][0] * sc0 + ts0;
            lst[mi][1] = lst[mi][1] * sc1 + ts1;

            #pragma unroll
            for (int ni = 0; ni < 8; ni++) {
                o[mi][ni][0] *= sc0; o[mi][ni][1] *= sc0;
                o[mi][ni][2] *= sc1; o[mi][ni][3] *= sc1;
            }
        }

        // ---- P to warp-private smem rows (tf32-rounded) ----
        #pragma unroll
        for (int mi = 0; mi < 2; mi++)
            #pragma unroll
            for (int ni = 0; ni < 8; ni++) {
                const int col = ni * 8 + 2 * cq;
                const int rA = (wr0 + mi * 16 + rq) * QPAD;
                const int rB = rA + 8 * QPAD;
                Ps[rA + col]     = tf32r(s[mi][ni][0]);
                Ps[rA + col + 1] = tf32r(s[mi][ni][1]);
                Ps[rB + col]     = tf32r(s[mi][ni][2]);
                Ps[rB + col + 1] = tf32r(s[mi][ni][3]);
            }
        __syncwarp();

        // ---- O += P @ V ----
        #pragma unroll
        for (int ks = 0; ks < 8; ks++) {
            const int k0 = ks * 8;
            uint32_t af[2][4];
            #pragma unroll
            for (int mi = 0; mi < 2; mi++) {
                const int rA = (wr0 + mi * 16 + rq) * QPAD;
                const int rB = rA + 8 * QPAD;
                af[mi][0] = __float_as_uint(Ps[rA + k0 + cq]);
                af[mi][1] = __float_as_uint(Ps[rB + k0 + cq]);
                af[mi][2] = __float_as_uint(Ps[rA + k0 + cq + 4]);
                af[mi][3] = __float_as_uint(Ps[rB + k0 + cq + 4]);
            }
            #pragma unroll
            for (int ni = 0; ni < 8; ni++) {
                uint32_t b0 = __float_as_uint(Vs[(k0 + cq)     * VPAD + ni * 8 + rq]);
                uint32_t b1 = __float_as_uint(Vs[(k0 + cq + 4) * VPAD + ni * 8 + rq]);
                mma_tf32_16x8x8(o[0][ni], af[0][0], af[0][1], af[0][2], af[0][3], b0, b1);
                mma_tf32_16x8x8(o[1][ni], af[1][0], af[1][1], af[1][2], af[1][3], b0, b1);
            }
        }
        __syncwarp();
    }

    // ---- normalize + write ctx [B,S,E] (tf32-rounded for GEMM2) ----
    #pragma unroll
    for (int mi = 0; mi < 2; mi++) {
        #pragma unroll
        for (int hh = 0; hh < 2; hh++) {
            const int row = gr[mi][hh];
            const float l = lst[mi][hh];
            const int pm = pmask[b * SEQ + row];
            const float inv = (l > 0.f && pm == 1) ? 1.f / l : 0.f;
            float* cp = ctx + (size_t)(b * SEQ + row) * EMB + h * DHEAD;
            #pragma unroll
            for (int ni = 0; ni < 8; ni++) {
                const int col = ni * 8 + 2 * cq;
                float2 v;
                v.x = tf32r(o[mi][ni][2 * hh]     * inv);
                v.y = tf32r(o[mi][ni][2 * hh + 1] * inv);
                *(float2*)(cp + col) = v;
            }
        }
    }
}

// ---------------------------------------------------------------------------
// Launch
// ---------------------------------------------------------------------------
extern "C" void kernel_launch(void* const* d_in, const int* in_sizes, int n_in,
                              void* d_out, int out_size)
{
    const float* x     = (const float*)d_in[0];
    const int*   pmask = (const int*)  d_in[1];
    const float* Wqkv  = (const float*)d_in[2];
    const float* bqkv  = (const float*)d_in[3];
    const float* Wo    = (const float*)d_in[4];
    const float* bo    = (const float*)d_in[5];
    float* out = (float*)d_out;

    float *qkv, *ctx, *xr, *wqkvr, *wor;
    cudaGetSymbolAddress((void**)&qkv,   g_qkv);
    cudaGetSymbolAddress((void**)&ctx,   g_ctx);
    cudaGetSymbolAddress((void**)&xr,    g_xr);
    cudaGetSymbolAddress((void**)&wqkvr, g_wqkvr);
    cudaGetSymbolAddress((void**)&wor,   g_wor);

    cudaFuncSetAttribute(mma_gemm_kernel,
                         cudaFuncAttributeMaxDynamicSharedMemorySize,
                         GEMM_SMEM_BYTES);
    cudaFuncSetAttribute(attn_mma_kernel,
                         cudaFuncAttributeMaxDynamicSharedMemorySize,
                         ATT_SMEM_BYTES);

    // 0) tf32 pre-round, single launch (x, Wqkv, Wo)
    {
        const int total = NX4 + NQ4 + NO4;
        round3_tf32_kernel<<<(total + 255) / 256, 256>>>(x, Wqkv, Wo,
                                                         xr, wqkvr, wor);
    }

    // 1) QKV projection (tf32 mma.sync), output tf32-rounded
    {
        dim3 grid(N1 / BN, M1 / BM);   // (24, 32) = 768 CTAs
        mma_gemm_kernel<<<grid, 256, GEMM_SMEM_BYTES>>>(xr, wqkvr, bqkv, qkv,
                                                        M1, N1, KDIM, 1);
    }

    // 2) Banded attention (tensor-core flash, 128-query tiles)
    {
        dim3 grid(SEQ / QTILE, BATCH * HEADS);   // (16, 16) = 256 CTAs
        attn_mma_kernel<<<grid, 128, ATT_SMEM_BYTES>>>(qkv, pmask, ctx);
    }

    // 3) Output projection (tf32 mma.sync), fp32 output
    {
        dim3 grid(EMB / BN, M1 / BM);   // (8, 32) = 256 CTAs
        mma_gemm_kernel<<<grid, 256, GEMM_SMEM_BYTES>>>(ctx, wor, bo, out,
                                                        M1, EMB, KDIM, 0);
    }
}

// round 17
// speedup vs baseline: 1.0703x; 1.0678x over previous
#include <cuda_runtime.h>
#include <cstdint>
#include <math.h>

// Problem constants (fixed by the reference)
#define BATCH   2
#define SEQ     2048
#define EMB     512
#define HEADS   8
#define DHEAD   64
#define WINHALF 128         // WIN/2

#define M1 (BATCH*SEQ)      // 4096 rows
#define N1 (3*EMB)          // 1536 (qkv)
#define KDIM EMB            // 512

// Scratch: __device__ globals (no allocation allowed anywhere)
__device__ float g_qkv[(size_t)M1 * N1];      // tf32-rounded qkv   ~25 MB
__device__ float g_ctx[(size_t)M1 * EMB];     // tf32-rounded ctx    ~8 MB
__device__ float g_xr[(size_t)M1 * KDIM];     // tf32-rounded x      ~8 MB
__device__ float g_wqkvr[(size_t)KDIM * N1];  // tf32-rounded Wqkv   ~3 MB
__device__ float g_wor[(size_t)KDIM * EMB];   // tf32-rounded Wo     ~1 MB

// ===========================================================================
// Helpers: mma.sync tf32 (SM80-compatible path, valid on compute_100)
// ===========================================================================
__device__ __forceinline__ uint32_t f2tf32(float x) {
    uint32_t r;
    asm("cvt.rna.tf32.f32 %0, %1;" : "=r"(r) : "f"(x));
    return r;
}
__device__ __forceinline__ float tf32r(float x) {
    return __uint_as_float(f2tf32(x));
}

__device__ __forceinline__ void mma_tf32_16x8x8(
    float* c, uint32_t a0, uint32_t a1, uint32_t a2, uint32_t a3,
    uint32_t b0, uint32_t b1)
{
    asm volatile(
        "mma.sync.aligned.m16n8k8.row.col.f32.tf32.tf32.f32 "
        "{%0,%1,%2,%3}, {%4,%5,%6,%7}, {%8,%9}, {%0,%1,%2,%3};"
        : "+f"(c[0]), "+f"(c[1]), "+f"(c[2]), "+f"(c[3])
        : "r"(a0), "r"(a1), "r"(a2), "r"(a3), "r"(b0), "r"(b1));
}

__device__ __forceinline__ uint32_t smem_u32(const void* p) {
    return (uint32_t)__cvta_generic_to_shared(p);
}

#define CP_ASYNC16(dst_u32, src_ptr) \
    asm volatile("cp.async.cg.shared.global [%0], [%1], 16;" \
                 :: "r"(dst_u32), "l"(src_ptr))
#define CP_COMMIT() asm volatile("cp.async.commit_group;" ::: "memory")
#define CP_WAIT(n)  asm volatile("cp.async.wait_group %0;" :: "n"(n) : "memory")

// ===========================================================================
// Fused tf32 rounding pre-pass: one launch for x, Wqkv, Wo (range dispatch)
// ===========================================================================
#define NX4 (M1 * KDIM / 4)
#define NQ4 (KDIM * N1 / 4)
#define NO4 (KDIM * EMB / 4)

__global__ void round3_tf32_kernel(const float* __restrict__ x,
                                   const float* __restrict__ wq,
                                   const float* __restrict__ wo,
                                   float* __restrict__ xr,
                                   float* __restrict__ wqr,
                                   float* __restrict__ wor)
{
    int i = blockIdx.x * blockDim.x + threadIdx.x;
    const float4* src;
    float4* dst;
    if (i < NX4)                 { src = (const float4*)x  + i;
                                   dst = (float4*)xr  + i; }
    else if (i < NX4 + NQ4)      { src = (const float4*)wq + (i - NX4);
                                   dst = (float4*)wqr + (i - NX4); }
    else if (i < NX4 + NQ4 + NO4){ src = (const float4*)wo + (i - NX4 - NQ4);
                                   dst = (float4*)wor + (i - NX4 - NQ4); }
    else return;
    float4 v = *src;
    v.x = tf32r(v.x); v.y = tf32r(v.y);
    v.z = tf32r(v.z); v.w = tf32r(v.w);
    *dst = v;
}

// ===========================================================================
// tf32 tensor-core GEMM (R12 config — best measured): C = A @ B + bias
// 128x128 CTA tile, BK=32, 2-stage cp.async, 8 warps (2x4), warp tile 64x32.
// 256 threads, launch_bounds(256,2). smem 71,680 B -> 2 CTAs/SM.
// ===========================================================================
#define BM 128
#define BN 128
#define BK 32
#define APAD 36    // As row stride (floats)
#define BPAD 136   // Bs row stride (floats)

#define GEMM_SMEM_BYTES ((2 * BM * APAD + 2 * BK * BPAD) * (int)sizeof(float))

__global__ __launch_bounds__(256, 2) void mma_gemm_kernel(
    const float* __restrict__ A, const float* __restrict__ B,
    const float* __restrict__ bias, float* __restrict__ C,
    int M, int N, int K, int round_out)
{
    extern __shared__ float smem[];
    float* AsBase = smem;                    // 2 stages of BM*APAD
    float* BsBase = smem + 2 * BM * APAD;    // 2 stages of BK*BPAD

    const int tid  = threadIdx.x;
    const int lane = tid & 31;
    const int wid  = tid >> 5;
    const int wm   = wid & 1;            // warp row (2)
    const int wn   = wid >> 1;           // warp col (4)
    const int m0   = blockIdx.y * BM;
    const int n0   = blockIdx.x * BN;

    const int aRow = wm * 64 + (lane >> 2);
    const int aCol = lane & 3;
    const int bCol = wn * 32 + (lane >> 2);
    const int bRow = lane & 3;

    float acc[4][4][4];
    #pragma unroll
    for (int mi = 0; mi < 4; mi++)
        #pragma unroll
        for (int ni = 0; ni < 4; ni++)
            #pragma unroll
            for (int r = 0; r < 4; r++) acc[mi][ni][r] = 0.f;

    const int nch = K / BK;   // 16

    auto load_tiles = [&](int s, int ch) {
        const int k0 = ch * BK;
        float* As_ = AsBase + s * BM * APAD;
        float* Bs_ = BsBase + s * BK * BPAD;
        // A: 128 rows x 32 floats -> 1024 float4, 4 per thread
        #pragma unroll
        for (int i = 0; i < 4; i++) {
            const int idx = tid + i * 256;
            const int row = idx >> 3;
            const int c4  = (idx & 7) << 2;
            const float* src = A + (size_t)(m0 + row) * K + k0 + c4;
            CP_ASYNC16(smem_u32(&As_[row * APAD + c4]), src);
        }
        // B: 32 rows x 128 floats -> 1024 float4, 4 per thread
        #pragma unroll
        for (int i = 0; i < 4; i++) {
            const int idx = tid + i * 256;
            const int row = idx >> 5;
            const int c4  = (idx & 31) << 2;
            const float* src = B + (size_t)(k0 + row) * N + n0 + c4;
            CP_ASYNC16(smem_u32(&Bs_[row * BPAD + c4]), src);
        }
        CP_COMMIT();
    };

    load_tiles(0, 0);

    for (int ch = 0; ch < nch; ch++) {
        const int s = ch & 1;
        if (ch + 1 < nch) {
            load_tiles(s ^ 1, ch + 1);
            CP_WAIT(1);
        } else {
            CP_WAIT(0);
        }
        __syncthreads();

        const float* As_ = AsBase + s * BM * APAD;
        const float* Bs_ = BsBase + s * BK * BPAD;

        #pragma unroll
        for (int ks = 0; ks < 4; ks++) {
            const int k0 = ks * 8;
            uint32_t bf[4][2];
            #pragma unroll
            for (int ni = 0; ni < 4; ni++) {
                bf[ni][0] = __float_as_uint(Bs_[(k0 + bRow)     * BPAD + bCol + ni * 8]);
                bf[ni][1] = __float_as_uint(Bs_[(k0 + bRow + 4) * BPAD + bCol + ni * 8]);
            }
            #pragma unroll
            for (int mi = 0; mi < 4; mi++) {
                const int r0 = (aRow + mi * 16) * APAD;
                const int r8 = (aRow + mi * 16 + 8) * APAD;
                uint32_t a0 = __float_as_uint(As_[r0 + k0 + aCol]);
                uint32_t a1 = __float_as_uint(As_[r8 + k0 + aCol]);
                uint32_t a2 = __float_as_uint(As_[r0 + k0 + aCol + 4]);
                uint32_t a3 = __float_as_uint(As_[r8 + k0 + aCol + 4]);
                #pragma unroll
                for (int ni = 0; ni < 4; ni++)
                    mma_tf32_16x8x8(acc[mi][ni], a0, a1, a2, a3,
                                    bf[ni][0], bf[ni][1]);
            }
        }
        __syncthreads();
    }

    // Epilogue: thread owns rows (crow + mi*16) and (crow + mi*16 + 8)
    const int crow = m0 + wm * 64 + (lane >> 2);
    const int ccol = n0 + wn * 32 + ((lane & 3) << 1);
    #pragma unroll
    for (int mi = 0; mi < 4; mi++) {
        #pragma unroll
        for (int ni = 0; ni < 4; ni++) {
            const int col = ccol + ni * 8;
            const float bx = bias[col], by = bias[col + 1];
            float2 v0, v1;
            v0.x = acc[mi][ni][0] + bx;  v0.y = acc[mi][ni][1] + by;
            v1.x = acc[mi][ni][2] + bx;  v1.y = acc[mi][ni][3] + by;
            if (round_out) {
                v0.x = tf32r(v0.x); v0.y = tf32r(v0.y);
                v1.x = tf32r(v1.x); v1.y = tf32r(v1.y);
            }
            *(float2*)(C + (size_t)(crow + mi * 16)     * N + col) = v0;
            *(float2*)(C + (size_t)(crow + mi * 16 + 8) * N + col) = v1;
        }
    }
}

// ===========================================================================
// Fused banded attention on tensor cores (flash-style, tf32 mma).
// 128-query tile, 4 warps, each warp owns 32 rows (2 x m16 tiles).
// 6 key-tiles of 64 cover the band (vs 10 per 128 rows at a 64-tile).
// qkv pre-rounded tf32; ctx written tf32-rounded for GEMM2.
// ===========================================================================
#define QTILE 128
#define QPAD 68
#define VPAD 72
#define ATT_SMEM_BYTES ((2 * QTILE * QPAD + 64 * QPAD + 64 * VPAD) * (int)sizeof(float) + 64 * (int)sizeof(int))

__global__ __launch_bounds__(128) void attn_mma_kernel(
    const float* __restrict__ qkv, const int* __restrict__ pmask,
    float* __restrict__ ctx)
{
    extern __shared__ float sm[];
    float* Qs = sm;                          // [128][68]
    float* Ks = Qs + QTILE * QPAD;           // [64][68]
    float* Ps = Ks + 64 * QPAD;              // [128][68]
    float* Vs = Ps + QTILE * QPAD;           // [64][72]
    int*   pms = (int*)(Vs + 64 * VPAD);     // [64]

    const int tid  = threadIdx.x;
    const int lane = tid & 31;
    const int wid  = tid >> 5;
    const int rq   = lane >> 2;    // 0..7
    const int cq   = lane & 3;     // 0..3
    const int wr0  = wid * 32;     // warp owns rows wr0..wr0+31

    const int r0 = blockIdx.x * QTILE;
    const int b  = blockIdx.y >> 3;
    const int h  = blockIdx.y & 7;

    const float* base = qkv + (size_t)b * SEQ * N1 + h * (3 * DHEAD);

    // Load Q tile: 128 rows x 64 cols = 2048 float4, 16 per thread
    #pragma unroll
    for (int i = 0; i < 16; i++) {
        const int idx = tid + i * 128;
        const int row = idx >> 4;
        const int c4  = (idx & 15) << 2;
        float4 v = *(const float4*)(base + (size_t)(r0 + row) * N1 + c4);
        float* q = Qs + row * QPAD + c4;
        q[0] = v.x * 0.125f; q[1] = v.y * 0.125f;
        q[2] = v.z * 0.125f; q[3] = v.w * 0.125f;
    }

    float o[2][8][4];
    #pragma unroll
    for (int mi = 0; mi < 2; mi++)
        #pragma unroll
        for (int ni = 0; ni < 8; ni++)
            #pragma unroll
            for (int r = 0; r < 4; r++) o[mi][ni][r] = 0.f;

    float mst[2][2], lst[2][2];
    #pragma unroll
    for (int mi = 0; mi < 2; mi++) {
        mst[mi][0] = -1e30f; mst[mi][1] = -1e30f;
        lst[mi][0] = 0.f;    lst[mi][1] = 0.f;
    }
    int gr[2][2];
    #pragma unroll
    for (int mi = 0; mi < 2; mi++) {
        gr[mi][0] = r0 + wr0 + mi * 16 + rq;
        gr[mi][1] = gr[mi][0] + 8;
    }

    for (int kt = 0; kt < 6; kt++) {
        const int c0 = r0 - WINHALF + kt * 64;
        if (c0 + 63 < 0 || c0 >= SEQ) continue;   // uniform across block

        __syncthreads();   // Q ready (first pass) / prev tile fully consumed

        // Load K,V tile (zero-fill out-of-range); pmask tile
        #pragma unroll
        for (int i = 0; i < 8; i++) {
            const int idx = tid + i * 128;
            const int row = idx >> 4;
            const int c4  = (idx & 15) << 2;
            const int gc  = c0 + row;
            float4 kv = make_float4(0.f, 0.f, 0.f, 0.f);
            float4 vv = make_float4(0.f, 0.f, 0.f, 0.f);
            if (gc >= 0 && gc < SEQ) {
                kv = *(const float4*)(base + (size_t)gc * N1 + DHEAD + c4);
                vv = *(const float4*)(base + (size_t)gc * N1 + 2 * DHEAD + c4);
            }
            float* kp = Ks + row * QPAD + c4;
            kp[0] = kv.x; kp[1] = kv.y; kp[2] = kv.z; kp[3] = kv.w;
            float* vp = Vs + row * VPAD + c4;
            vp[0] = vv.x; vp[1] = vv.y; vp[2] = vv.z; vp[3] = vv.w;
        }
        if (tid < 64) {
            const int gc = c0 + tid;
            pms[tid] = (gc >= 0 && gc < SEQ) ? pmask[b * SEQ + gc] : 0;
        }
        __syncthreads();

        // ---- S = Q @ K^T : rows wr0..wr0+31, cols 0..63 ----
        float s[2][8][4];
        #pragma unroll
        for (int mi = 0; mi < 2; mi++)
            #pragma unroll
            for (int ni = 0; ni < 8; ni++)
                #pragma unroll
                for (int r = 0; r < 4; r++) s[mi][ni][r] = 0.f;

        #pragma unroll
        for (int ks = 0; ks < 8; ks++) {
            const int k0 = ks * 8;
            uint32_t af[2][4];
            #pragma unroll
            for (int mi = 0; mi < 2; mi++) {
                const int rA = (wr0 + mi * 16 + rq) * QPAD;
                const int rB = rA + 8 * QPAD;
                af[mi][0] = __float_as_uint(Qs[rA + k0 + cq]);
                af[mi][1] = __float_as_uint(Qs[rB + k0 + cq]);
                af[mi][2] = __float_as_uint(Qs[rA + k0 + cq + 4]);
                af[mi][3] = __float_as_uint(Qs[rB + k0 + cq + 4]);
            }
            #pragma unroll
            for (int ni = 0; ni < 8; ni++) {
                uint32_t b0 = __float_as_uint(Ks[(ni * 8 + rq) * QPAD + k0 + cq]);
                uint32_t b1 = __float_as_uint(Ks[(ni * 8 + rq) * QPAD + k0 + cq + 4]);
                mma_tf32_16x8x8(s[0][ni], af[0][0], af[0][1], af[0][2], af[0][3], b0, b1);
                mma_tf32_16x8x8(s[1][ni], af[1][0], af[1][1], af[1][2], af[1][3], b0, b1);
            }
        }

        // ---- band + padding mask ----
        #pragma unroll
        for (int mi = 0; mi < 2; mi++)
            #pragma unroll
            for (int ni = 0; ni < 8; ni++)
                #pragma unroll
                for (int d = 0; d < 2; d++) {
                    const int lc = ni * 8 + 2 * cq + d;
                    const int gc = c0 + lc;
                    const bool cvalid = (pms[lc] == 1);
                    const int d0 = gc - gr[mi][0];
                    const int d1 = gc - gr[mi][1];
                    if (!cvalid || d0 > WINHALF || d0 < -WINHALF) s[mi][ni][d]     = -1e30f;
                    if (!cvalid || d1 > WINHALF || d1 < -WINHALF) s[mi][ni][d + 2] = -1e30f;
                }

        // ---- online softmax (quad-local), exp in place ----
        #pragma unroll
        for (int mi = 0; mi < 2; mi++) {
            float tm0 = -1e30f, tm1 = -1e30f;
            #pragma unroll
            for (int ni = 0; ni < 8; ni++) {
                tm0 = fmaxf(tm0, fmaxf(s[mi][ni][0], s[mi][ni][1]));
                tm1 = fmaxf(tm1, fmaxf(s[mi][ni][2], s[mi][ni][3]));
            }
            tm0 = fmaxf(tm0, __shfl_xor_sync(0xffffffffu, tm0, 1));
            tm0 = fmaxf(tm0, __shfl_xor_sync(0xffffffffu, tm0, 2));
            tm1 = fmaxf(tm1, __shfl_xor_sync(0xffffffffu, tm1, 1));
            tm1 = fmaxf(tm1, __shfl_xor_sync(0xffffffffu, tm1, 2));

            const float mn0 = fmaxf(mst[mi][0], tm0);
            const float mn1 = fmaxf(mst[mi][1], tm1);
            const float sc0 = __expf(mst[mi][0] - mn0);
            const float sc1 = __expf(mst[mi][1] - mn1);
            mst[mi][0] = mn0; mst[mi][1] = mn1;

            float ts0 = 0.f, ts1 = 0.f;
            #pragma unroll
            for (int ni = 0; ni < 8; ni++) {
                s[mi][ni][0] = (s[mi][ni][0] > -1e29f) ? __expf(s[mi][ni][0] - mn0) : 0.f;
                s[mi][ni][1] = (s[mi][ni][1] > -1e29f) ? __expf(s[mi][ni][1] - mn0) : 0.f;
                s[mi][ni][2] = (s[mi][ni][2] > -1e29f) ? __expf(s[mi][ni][2] - mn1) : 0.f;
                s[mi][ni][3] = (s[mi][ni][3] > -1e29f) ? __expf(s[mi][ni][3] - mn1) : 0.f;
                ts0 += s[mi][ni][0] + s[mi][ni][1];
                ts1 += s[mi][ni][2] + s[mi][ni][3];
            }
            ts0 += __shfl_xor_sync(0xffffffffu, ts0, 1);
            ts0 += __shfl_xor_sync(0xffffffffu, ts0, 2);
            ts1 += __shfl_xor_sync(0xffffffffu, ts1, 1);
            ts1 += __shfl_xor_sync(0xffffffffu, ts1, 2);
            lst[mi][0] = lst[mi][0] * sc0 + ts0;
            lst[mi][1] = lst[mi][1] * sc1 + ts1;

            #pragma unroll
            for (int ni = 0; ni < 8; ni++) {
                o[mi][ni][0] *= sc0; o[mi][ni][1] *= sc0;
                o[mi][ni][2] *= sc1; o[mi][ni][3] *= sc1;
            }
        }

        // ---- P to warp-private smem rows (tf32-rounded) ----
        #pragma unroll
        for (int mi = 0; mi < 2; mi++)
            #pragma unroll
            for (int ni = 0; ni < 8; ni++) {
                const int col = ni * 8 + 2 * cq;
                const int rA = (wr0 + mi * 16 + rq) * QPAD;
                const int rB = rA + 8 * QPAD;
                Ps[rA + col]     = tf32r(s[mi][ni][0]);
                Ps[rA + col + 1] = tf32r(s[mi][ni][1]);
                Ps[rB + col]     = tf32r(s[mi][ni][2]);
                Ps[rB + col + 1] = tf32r(s[mi][ni][3]);
            }
        __syncwarp();

        // ---- O += P @ V ----
        #pragma unroll
        for (int ks = 0; ks < 8; ks++) {
            const int k0 = ks * 8;
            uint32_t af[2][4];
            #pragma unroll
            for (int mi = 0; mi < 2; mi++) {
                const int rA = (wr0 + mi * 16 + rq) * QPAD;
                const int rB = rA + 8 * QPAD;
                af[mi][0] = __float_as_uint(Ps[rA + k0 + cq]);
                af[mi][1] = __float_as_uint(Ps[rB + k0 + cq]);
                af[mi][2] = __float_as_uint(Ps[rA + k0 + cq + 4]);
                af[mi][3] = __float_as_uint(Ps[rB + k0 + cq + 4]);
            }
            #pragma unroll
            for (int ni = 0; ni < 8; ni++) {
                uint32_t b0 = __float_as_uint(Vs[(k0 + cq)     * VPAD + ni * 8 + rq]);
                uint32_t b1 = __float_as_uint(Vs[(k0 + cq + 4) * VPAD + ni * 8 + rq]);
                mma_tf32_16x8x8(o[0][ni], af[0][0], af[0][1], af[0][2], af[0][3], b0, b1);
                mma_tf32_16x8x8(o[1][ni], af[1][0], af[1][1], af[1][2], af[1][3], b0, b1);
            }
        }
        __syncwarp();
    }

    // ---- normalize + write ctx [B,S,E] (tf32-rounded for GEMM2) ----
    #pragma unroll
    for (int mi = 0; mi < 2; mi++) {
        #pragma unroll
        for (int hh = 0; hh < 2; hh++) {
            const int row = gr[mi][hh];
            const float l = lst[mi][hh];
            const int pm = pmask[b * SEQ + row];
            const float inv = (l > 0.f && pm == 1) ? 1.f / l : 0.f;
            float* cp = ctx + (size_t)(b * SEQ + row) * EMB + h * DHEAD;
            #pragma unroll
            for (int ni = 0; ni < 8; ni++) {
                const int col = ni * 8 + 2 * cq;
                float2 v;
                v.x = tf32r(o[mi][ni][2 * hh]     * inv);
                v.y = tf32r(o[mi][ni][2 * hh + 1] * inv);
                *(float2*)(cp + col) = v;
            }
        }
    }
}

// ---------------------------------------------------------------------------
// Launch
// ---------------------------------------------------------------------------
extern "C" void kernel_launch(void* const* d_in, const int* in_sizes, int n_in,
                              void* d_out, int out_size)
{
    const float* x     = (const float*)d_in[0];
    const int*   pmask = (const int*)  d_in[1];
    const float* Wqkv  = (const float*)d_in[2];
    const float* bqkv  = (const float*)d_in[3];
    const float* Wo    = (const float*)d_in[4];
    const float* bo    = (const float*)d_in[5];
    float* out = (float*)d_out;

    float *qkv, *ctx, *xr, *wqkvr, *wor;
    cudaGetSymbolAddress((void**)&qkv,   g_qkv);
    cudaGetSymbolAddress((void**)&ctx,   g_ctx);
    cudaGetSymbolAddress((void**)&xr,    g_xr);
    cudaGetSymbolAddress((void**)&wqkvr, g_wqkvr);
    cudaGetSymbolAddress((void**)&wor,   g_wor);

    cudaFuncSetAttribute(mma_gemm_kernel,
                         cudaFuncAttributeMaxDynamicSharedMemorySize,
                         GEMM_SMEM_BYTES);
    cudaFuncSetAttribute(attn_mma_kernel,
                         cudaFuncAttributeMaxDynamicSharedMemorySize,
                         ATT_SMEM_BYTES);

    // 0) tf32 pre-round, single launch (x, Wqkv, Wo)
    {
        const int total = NX4 + NQ4 + NO4;
        round3_tf32_kernel<<<(total + 255) / 256, 256>>>(x, Wqkv, Wo,
                                                         xr, wqkvr, wor);
    }

    // 1) QKV projection (tf32 mma.sync), output tf32-rounded
    {
        dim3 grid(N1 / BN, M1 / BM);   // (12, 32) = 384 CTAs
        mma_gemm_kernel<<<grid, 256, GEMM_SMEM_BYTES>>>(xr, wqkvr, bqkv, qkv,
                                                        M1, N1, KDIM, 1);
    }

    // 2) Banded attention (tensor-core flash, 128-query tiles)
    {
        dim3 grid(SEQ / QTILE, BATCH * HEADS);   // (16, 16) = 256 CTAs
        attn_mma_kernel<<<grid, 128, ATT_SMEM_BYTES>>>(qkv, pmask, ctx);
    }

    // 3) Output projection (tf32 mma.sync), fp32 output
    {
        dim3 grid(EMB / BN, M1 / BM);   // (4, 32) = 128 CTAs
        mma_gemm_kernel<<<grid, 256, GEMM_SMEM_BYTES>>>(ctx, wor, bo, out,
                                                        M1, EMB, KDIM, 0);
    }
}